// round 1
// baseline (speedup 1.0000x reference)
#include <cuda_runtime.h>
#include <math.h>

#define N_NODES 8192
#define F_IN    256
#define F_OUT   64
#define ALPHA   0.2f

// Scratch (no allocation allowed) ---------------------------------------
__device__ __align__(16) float g_Wh[N_NODES * F_OUT];   // 2 MB
__device__ float g_wh1[N_NODES];
__device__ float g_wh2[N_NODES];
__device__ float g_Sall[F_OUT];

// ------------------------------------------------------------------------
// Kernel 1: Wh = h @ W   (8192x256 @ 256x64)
// grid 128 blocks, 256 threads; 64x64 output tile, 4x4 register blocking.
// ------------------------------------------------------------------------
__global__ __launch_bounds__(256) void k_gemm(const float* __restrict__ h,
                                              const float* __restrict__ W) {
    __shared__ __align__(16) float hs[64 * 65];   // [row][k], pad 65 avoids bank conflicts
    __shared__ __align__(16) float Ws[64 * 64];   // [k][c]

    const int t  = threadIdx.x;
    const int tx = t & 15;    // column group (4 cols each)
    const int ty = t >> 4;    // row group    (4 rows each)
    const int u0 = blockIdx.x * 64;

    float acc[4][4] = {};

    for (int kc = 0; kc < 4; kc++) {
        // Load h tile: 64 rows x 64 k (coalesced reads, conflict-free writes)
        #pragma unroll
        for (int i = 0; i < 16; i++) {
            int idx = i * 256 + t;
            int r = idx >> 6, k = idx & 63;
            hs[r * 65 + k] = h[(size_t)(u0 + r) * F_IN + kc * 64 + k];
        }
        // Load W tile: 64 k x 64 c
        #pragma unroll
        for (int i = 0; i < 16; i++) {
            int idx = i * 256 + t;
            int k = idx >> 6, c = idx & 63;
            Ws[k * 64 + c] = W[(size_t)(kc * 64 + k) * F_OUT + c];
        }
        __syncthreads();

        #pragma unroll
        for (int kk = 0; kk < 64; kk++) {
            float4 wv = *(const float4*)&Ws[kk * 64 + tx * 4];
            float hv[4];
            #pragma unroll
            for (int r = 0; r < 4; r++) hv[r] = hs[(ty * 4 + r) * 65 + kk];
            #pragma unroll
            for (int r = 0; r < 4; r++) {
                acc[r][0] += hv[r] * wv.x;
                acc[r][1] += hv[r] * wv.y;
                acc[r][2] += hv[r] * wv.z;
                acc[r][3] += hv[r] * wv.w;
            }
        }
        __syncthreads();
    }

    #pragma unroll
    for (int r = 0; r < 4; r++) {
        float4 o = make_float4(acc[r][0], acc[r][1], acc[r][2], acc[r][3]);
        *(float4*)&g_Wh[(size_t)(u0 + ty * 4 + r) * F_OUT + tx * 4] = o;
    }
}

// ------------------------------------------------------------------------
// Kernel 2: wh1[u] = dot(Wh[u], a[64:128]), wh2[u] = dot(Wh[u], a[0:64])
// grid 8192 blocks, 64 threads.
// ------------------------------------------------------------------------
__global__ __launch_bounds__(64) void k_wh(const float* __restrict__ a) {
    const int u = blockIdx.x;
    const int c = threadIdx.x;
    float v  = g_Wh[(size_t)u * F_OUT + c];
    float s1 = v * a[F_OUT + c];   // source/row term uses a[f_out:]
    float s2 = v * a[c];           // destination/col term uses a[:f_out]
    #pragma unroll
    for (int off = 16; off; off >>= 1) {
        s1 += __shfl_down_sync(0xFFFFFFFFu, s1, off);
        s2 += __shfl_down_sync(0xFFFFFFFFu, s2, off);
    }
    __shared__ float r1[2], r2[2];
    if ((c & 31) == 0) { r1[c >> 5] = s1; r2[c >> 5] = s2; }
    __syncthreads();
    if (c == 0) {
        g_wh1[u] = r1[0] + r1[1];
        g_wh2[u] = r2[0] + r2[1];
    }
}

// ------------------------------------------------------------------------
// Kernel 3: Sall[c] = sum_u Wh[u][c]   (deterministic fixed tree)
// grid 64 blocks (one per channel), 256 threads.
// ------------------------------------------------------------------------
__global__ __launch_bounds__(256) void k_colsum() {
    const int c = blockIdx.x;
    const int t = threadIdx.x;
    float s = 0.f;
    for (int u = t; u < N_NODES; u += 256)
        s += g_Wh[(size_t)u * F_OUT + c];
    __shared__ float sm[256];
    sm[t] = s;
    __syncthreads();
    #pragma unroll
    for (int off = 128; off; off >>= 1) {
        if (t < off) sm[t] += sm[t + off];
        __syncthreads();
    }
    if (t == 0) g_Sall[c] = sm[0];
}

// ------------------------------------------------------------------------
// Kernel 4: main — one block per row u.
// 8 warps each scan 1024 columns of adj[u,:] (float4 + ballot). For each
// edge i, all 32 lanes accumulate wt*Wh[i][lane] and wt*Wh[i][lane+32];
// per-warp partials reduced in fixed order (deterministic). Softmax via
// identity: h' = (Sall + sum wt*Wh) / (8192 + sum wt), wt = exp(lrelu(e))-1.
// ------------------------------------------------------------------------
__global__ __launch_bounds__(256) void k_main(const float* __restrict__ adj,
                                              float* __restrict__ out) {
    const int u = blockIdx.x;
    const int t = threadIdx.x;
    const int w = t >> 5;     // warp 0..7
    const int l = t & 31;

    const float4* __restrict__ arow = (const float4*)(adj + (size_t)u * N_NODES);
    const float w1 = g_wh1[u];

    float acc0 = 0.f, acc1 = 0.f, den = 0.f;

    #pragma unroll
    for (int j = 0; j < 8; j++) {
        const int f4base = w * 256 + j * 32;          // float4 index base for this warp
        float4 v = arow[f4base + l];

        #pragma unroll
        for (int comp = 0; comp < 4; comp++) {
            float vc = (comp == 0) ? v.x : (comp == 1) ? v.y : (comp == 2) ? v.z : v.w;
            unsigned m = __ballot_sync(0xFFFFFFFFu, vc != 0.f);
            while (m) {
                int b = __ffs(m) - 1;
                m &= m - 1;
                int i = (f4base + b) * 4 + comp;      // edge column, derived from bit index
                float e = w1 + g_wh2[i];
                e = (e >= 0.f) ? e : ALPHA * e;
                float wt = expf(e) - 1.f;
                den  += wt;
                acc0 += wt * g_Wh[(size_t)i * F_OUT + l];
                acc1 += wt * g_Wh[(size_t)i * F_OUT + 32 + l];
            }
        }
    }

    __shared__ float sacc[8][64];
    __shared__ float sden[8];
    sacc[w][l]      = acc0;
    sacc[w][l + 32] = acc1;
    if (l == 0) sden[w] = den;
    __syncthreads();

    if (t < 64) {
        float num = g_Sall[t];
        float d   = (float)N_NODES;
        #pragma unroll
        for (int ww = 0; ww < 8; ww++) {
            num += sacc[ww][t];
            d   += sden[ww];
        }
        float x = num / d;
        out[(size_t)u * F_OUT + t] = (x > 0.f) ? x : expm1f(x);
    }
}

// ------------------------------------------------------------------------
extern "C" void kernel_launch(void* const* d_in, const int* in_sizes, int n_in,
                              void* d_out, int out_size) {
    const float* h   = (const float*)d_in[0];
    const float* adj = (const float*)d_in[1];
    const float* W   = (const float*)d_in[2];
    const float* a   = (const float*)d_in[3];
    float* out = (float*)d_out;

    k_gemm  <<<N_NODES / 64, 256>>>(h, W);
    k_wh    <<<N_NODES, 64>>>(a);
    k_colsum<<<F_OUT, 256>>>();
    k_main  <<<N_NODES, 256>>>(adj, out);
}

// round 2
// speedup vs baseline: 1.1789x; 1.1789x over previous
#include <cuda_runtime.h>
#include <math.h>

#define N_NODES 8192
#define F_IN    256
#define F_OUT   64
#define ALPHA   0.2f

// Scratch (no allocation allowed) ---------------------------------------
__device__ __align__(16) float g_Wh[N_NODES * F_OUT];   // 2 MB
__device__ float g_wh1[N_NODES];
__device__ float g_wh2[N_NODES];
__device__ float g_Sall[F_OUT];

// ------------------------------------------------------------------------
// Kernel 1: Wh = h @ W  (8192x256 @ 256x64), fused wh1/wh2 epilogue.
// grid 128 blocks, 256 threads; 64x64 tile, 4x4 register blocking,
// vectorized LDS (float4), 4-kk inner steps.
// ------------------------------------------------------------------------
__global__ __launch_bounds__(256) void k_gemm(const float* __restrict__ h,
                                              const float* __restrict__ W,
                                              const float* __restrict__ a) {
    __shared__ __align__(16) float hs[64 * 68];   // [row][k], pad 68 (16B-aligned rows)
    __shared__ __align__(16) float Ws[64 * 64];   // [k][c]

    const int t  = threadIdx.x;
    const int tx = t & 15;    // column group (4 cols each)
    const int ty = t >> 4;    // row group    (4 rows each)
    const int u0 = blockIdx.x * 64;

    float acc[4][4] = {};

    for (int kc = 0; kc < 4; kc++) {
        // Load h tile: 64 rows x 64 k, float4-vectorized (1024 float4s)
        #pragma unroll
        for (int i = 0; i < 4; i++) {
            int idx4 = i * 256 + t;
            int r = idx4 >> 4, k4 = idx4 & 15;
            *(float4*)&hs[r * 68 + k4 * 4] =
                *(const float4*)&h[(size_t)(u0 + r) * F_IN + kc * 64 + k4 * 4];
        }
        // Load W tile: 64 k x 64 c
        #pragma unroll
        for (int i = 0; i < 4; i++) {
            int idx4 = i * 256 + t;
            int k = idx4 >> 4, c4 = idx4 & 15;
            *(float4*)&Ws[k * 64 + c4 * 4] =
                *(const float4*)&W[(size_t)(kc * 64 + k) * F_OUT + c4 * 4];
        }
        __syncthreads();

        #pragma unroll
        for (int kk = 0; kk < 64; kk += 4) {
            float4 wv[4], hv[4];
            #pragma unroll
            for (int q = 0; q < 4; q++)
                wv[q] = *(const float4*)&Ws[(kk + q) * 64 + tx * 4];
            #pragma unroll
            for (int r = 0; r < 4; r++)
                hv[r] = *(const float4*)&hs[(ty * 4 + r) * 68 + kk];
            #pragma unroll
            for (int r = 0; r < 4; r++) {
                acc[r][0] += hv[r].x * wv[0].x + hv[r].y * wv[1].x + hv[r].z * wv[2].x + hv[r].w * wv[3].x;
                acc[r][1] += hv[r].x * wv[0].y + hv[r].y * wv[1].y + hv[r].z * wv[2].y + hv[r].w * wv[3].y;
                acc[r][2] += hv[r].x * wv[0].z + hv[r].y * wv[1].z + hv[r].z * wv[2].z + hv[r].w * wv[3].z;
                acc[r][3] += hv[r].x * wv[0].w + hv[r].y * wv[1].w + hv[r].z * wv[2].w + hv[r].w * wv[3].w;
            }
        }
        __syncthreads();
    }

    // Store Wh tile
    #pragma unroll
    for (int r = 0; r < 4; r++) {
        float4 o = make_float4(acc[r][0], acc[r][1], acc[r][2], acc[r][3]);
        *(float4*)&g_Wh[(size_t)(u0 + ty * 4 + r) * F_OUT + tx * 4] = o;
    }

    // Fused epilogue: wh1[u] = Wh[u].a[64:128], wh2[u] = Wh[u].a[0:64]
    // Row u0+ty*4+r is spread over the 16 threads sharing ty (one 16-lane group).
    float4 a1v = *(const float4*)&a[F_OUT + tx * 4];  // source/row term
    float4 a2v = *(const float4*)&a[tx * 4];          // destination/col term
    #pragma unroll
    for (int r = 0; r < 4; r++) {
        float s1 = acc[r][0] * a1v.x + acc[r][1] * a1v.y + acc[r][2] * a1v.z + acc[r][3] * a1v.w;
        float s2 = acc[r][0] * a2v.x + acc[r][1] * a2v.y + acc[r][2] * a2v.z + acc[r][3] * a2v.w;
        #pragma unroll
        for (int off = 8; off; off >>= 1) {
            s1 += __shfl_xor_sync(0xFFFFFFFFu, s1, off);
            s2 += __shfl_xor_sync(0xFFFFFFFFu, s2, off);
        }
        if (tx == 0) {
            g_wh1[u0 + ty * 4 + r] = s1;
            g_wh2[u0 + ty * 4 + r] = s2;
        }
    }
}

// ------------------------------------------------------------------------
// Kernel 2: Sall[c] = sum_u Wh[u][c]  (deterministic fixed tree; L2-resident)
// ------------------------------------------------------------------------
__global__ __launch_bounds__(256) void k_colsum() {
    const int c = blockIdx.x;
    const int t = threadIdx.x;
    float s = 0.f;
    for (int u = t; u < N_NODES; u += 256)
        s += g_Wh[(size_t)u * F_OUT + c];
    __shared__ float sm[256];
    sm[t] = s;
    __syncthreads();
    #pragma unroll
    for (int off = 128; off; off >>= 1) {
        if (t < off) sm[t] += sm[t + off];
        __syncthreads();
    }
    if (t == 0) g_Sall[c] = sm[0];
}

// ------------------------------------------------------------------------
// Kernel 3: main — one block per row u, 8 warps x 1024 columns each.
// Front-batched streaming loads (MLP=8), integer nonzero tests, group-level
// early-out ballot, warp-cooperative Wh gather, fixed-order deterministic
// reduction. Softmax identity:
//   h' = (Sall + sum wt*Wh) / (N + sum wt),  wt = exp(lrelu(e)) - 1.
// ------------------------------------------------------------------------
__global__ __launch_bounds__(256) void k_main(const float* __restrict__ adj,
                                              float* __restrict__ out) {
    const int u = blockIdx.x;
    const int t = threadIdx.x;
    const int w = t >> 5;     // warp 0..7
    const int l = t & 31;

    const uint4* __restrict__ arow = (const uint4*)(adj + (size_t)u * N_NODES);
    const float w1 = g_wh1[u];

    // Front-batch all 8 x 16B streaming loads: MLP=8 per thread, no L2 pollution.
    uint4 v[8];
    #pragma unroll
    for (int j = 0; j < 8; j++)
        v[j] = __ldcs(&arow[w * 256 + j * 32 + l]);

    float acc0 = 0.f, acc1 = 0.f, den = 0.f;

    #pragma unroll
    for (int j = 0; j < 8; j++) {
        // Whole-group early out: ~60% of 128-value groups have zero edges.
        unsigned any = v[j].x | v[j].y | v[j].z | v[j].w;
        if (__ballot_sync(0xFFFFFFFFu, any != 0u) == 0u) continue;

        const int f4base = w * 256 + j * 32;
        #pragma unroll
        for (int comp = 0; comp < 4; comp++) {
            unsigned vc = (comp == 0) ? v[j].x : (comp == 1) ? v[j].y
                        : (comp == 2) ? v[j].z : v[j].w;
            unsigned m = __ballot_sync(0xFFFFFFFFu, vc != 0u);
            while (m) {
                int b = __ffs(m) - 1;
                m &= m - 1;
                int i = (f4base + b) * 4 + comp;      // edge column
                float e = w1 + g_wh2[i];
                e = (e >= 0.f) ? e : ALPHA * e;
                float wt = __expf(e) - 1.f;
                den  += wt;
                acc0 += wt * g_Wh[i * F_OUT + l];
                acc1 += wt * g_Wh[i * F_OUT + 32 + l];
            }
        }
    }

    __shared__ float sacc[8][64];
    __shared__ float sden[8];
    sacc[w][l]      = acc0;
    sacc[w][l + 32] = acc1;
    if (l == 0) sden[w] = den;
    __syncthreads();

    if (t < 64) {
        float num = g_Sall[t];
        float d   = (float)N_NODES;
        #pragma unroll
        for (int ww = 0; ww < 8; ww++) {
            num += sacc[ww][t];
            d   += sden[ww];
        }
        float x = num / d;
        out[(size_t)u * F_OUT + t] = (x > 0.f) ? x : expm1f(x);
    }
}

// ------------------------------------------------------------------------
extern "C" void kernel_launch(void* const* d_in, const int* in_sizes, int n_in,
                              void* d_out, int out_size) {
    const float* h   = (const float*)d_in[0];
    const float* adj = (const float*)d_in[1];
    const float* W   = (const float*)d_in[2];
    const float* a   = (const float*)d_in[3];
    float* out = (float*)d_out;

    k_gemm  <<<N_NODES / 64, 256>>>(h, W, a);
    k_colsum<<<F_OUT, 256>>>();
    k_main  <<<N_NODES, 256>>>(adj, out);
}